// round 16
// baseline (speedup 1.0000x reference)
#include <cuda_runtime.h>
#include <cuda_bf16.h>
#include <cuda_fp16.h>
#include <math.h>
#include <stdint.h>

#define BB    2
#define SS    2048
#define MEMN  512
#define KN    2560
#define HN    16
#define DH    64
#define DM    1024
#define LPOS  (2*KN-1)        /* 5119 */
#define SCALE_F 0.03125f      /* 1/sqrt(1024) = 2^-5 */
#define QSCALE  (0.03125f * 1.44269504f)   /* fold log2e into Q */
#define EXP2_SHIFT 5.77078016f             /* 4 * log2e */
#define EPSF  1e-5f
#define NEG_BIG (-1e30f)

// ------------------- device scratch (no allocation allowed) -------------------
__device__ float g_cn [BB*KN*DM];        // LN([memory; hidden]) fp32 (residual)
__device__ __align__(16) __half g_cn_f [BB*KN*DM];
__device__ __align__(16) __half g_qf[BB*HN*SS*DH];
__device__ __align__(16) __half g_kf[BB*HN*KN*DH];
__device__ __align__(16) __half g_vf[BB*HN*KN*DH];
__device__ __align__(16) __half g_pf[BB*LPOS*DH];
__device__ __align__(16) __half g_wt_f [3*DM*DM];
__device__ __align__(16) __nv_bfloat16 g_atth[BB*SS*DM], g_attl[BB*SS*DM];
__device__ __align__(16) __nv_bfloat16 g_wo_h [DM*DM];
__device__ __align__(16) __nv_bfloat16 g_wo_l [DM*DM];

// ========================= helpers =========================
__device__ __forceinline__ uint32_t smem_u32(const void* p) {
    uint32_t a;
    asm("{ .reg .u64 t; cvta.to.shared.u64 t, %1; cvt.u32.u64 %0, t; }" : "=r"(a) : "l"(p));
    return a;
}
__device__ __forceinline__ void ldmatrix_x4(uint32_t* r, uint32_t addr) {
    asm volatile("ldmatrix.sync.aligned.m8n8.x4.shared.b16 {%0,%1,%2,%3}, [%4];"
        : "=r"(r[0]), "=r"(r[1]), "=r"(r[2]), "=r"(r[3]) : "r"(addr));
}
__device__ __forceinline__ void ldmatrix_x4_trans(uint32_t* r, uint32_t addr) {
    asm volatile("ldmatrix.sync.aligned.m8n8.x4.trans.shared.b16 {%0,%1,%2,%3}, [%4];"
        : "=r"(r[0]), "=r"(r[1]), "=r"(r[2]), "=r"(r[3]) : "r"(addr));
}
__device__ __forceinline__ void ldmatrix_x2(uint32_t* r, uint32_t addr) {
    asm volatile("ldmatrix.sync.aligned.m8n8.x2.shared.b16 {%0,%1}, [%2];"
        : "=r"(r[0]), "=r"(r[1]) : "r"(addr));
}
__device__ __forceinline__ void mma_bf16(float* d, const uint32_t* a, const uint32_t* b) {
    asm volatile(
        "mma.sync.aligned.m16n8k16.row.col.f32.bf16.bf16.f32 "
        "{%0,%1,%2,%3}, {%4,%5,%6,%7}, {%8,%9}, {%0,%1,%2,%3};"
        : "+f"(d[0]), "+f"(d[1]), "+f"(d[2]), "+f"(d[3])
        : "r"(a[0]), "r"(a[1]), "r"(a[2]), "r"(a[3]), "r"(b[0]), "r"(b[1]));
}
__device__ __forceinline__ void mma_f16(float* d, const uint32_t* a, const uint32_t* b) {
    asm volatile(
        "mma.sync.aligned.m16n8k16.row.col.f32.f16.f16.f32 "
        "{%0,%1,%2,%3}, {%4,%5,%6,%7}, {%8,%9}, {%0,%1,%2,%3};"
        : "+f"(d[0]), "+f"(d[1]), "+f"(d[2]), "+f"(d[3])
        : "r"(a[0]), "r"(a[1]), "r"(a[2]), "r"(a[3]), "r"(b[0]), "r"(b[1]));
}
#define CP_ASYNC16(dst, src) \
    asm volatile("cp.async.cg.shared.global [%0], [%1], 16;" :: "r"(dst), "l"(src))
#define CP_COMMIT() asm volatile("cp.async.commit_group;" ::: "memory")
#define CP_WAIT(N)  asm volatile("cp.async.wait_group %0;" :: "n"(N) : "memory")

__device__ __forceinline__ void store_split2(__nv_bfloat16* dh, __nv_bfloat16* dl,
                                             size_t off, float a, float b) {
    __nv_bfloat16 h0 = __float2bfloat16(a), h1 = __float2bfloat16(b);
    __nv_bfloat16 q0 = __float2bfloat16(a - __bfloat162float(h0));
    __nv_bfloat16 q1 = __float2bfloat16(b - __bfloat162float(h1));
    *(__nv_bfloat162*)(dh + off) = __halves2bfloat162(h0, h1);
    *(__nv_bfloat162*)(dl + off) = __halves2bfloat162(q0, q1);
}

// 64B-row tile swizzle: r in [0,128), s in [0,4) 16B slots. Tile = 8KB.
__device__ __forceinline__ uint32_t gsw(int r, int s) {
    return (uint32_t)((r >> 1) * 128 + ((((r & 1) << 2) | s) ^ ((r >> 1) & 7)) * 16);
}

// =========================== LayerNorm (+ fp16 store) ===========================
__global__ void __launch_bounds__(256) ln_kernel(const float* __restrict__ hidden,
                                                 const float* __restrict__ memory,
                                                 const float* __restrict__ gamma,
                                                 const float* __restrict__ beta) {
    __shared__ float red[8];
    __shared__ float s_mu, s_inv;
    const int row = blockIdx.x;
    const int b = row / KN, t = row % KN;
    const float* src = (t < MEMN) ? (memory + ((size_t)b*MEMN + t)*DM)
                                  : (hidden + ((size_t)b*SS + (t - MEMN))*DM);
    const int tid = threadIdx.x;
    float4 x = *(const float4*)(src + tid*4);

    float s = x.x + x.y + x.z + x.w;
    #pragma unroll
    for (int o = 16; o; o >>= 1) s += __shfl_xor_sync(0xffffffffu, s, o);
    if ((tid & 31) == 0) red[tid >> 5] = s;
    __syncthreads();
    if (tid == 0) {
        float tot = 0.f;
        #pragma unroll
        for (int i = 0; i < 8; i++) tot += red[i];
        s_mu = tot * (1.0f / DM);
    }
    __syncthreads();
    const float mu = s_mu;
    float d0 = x.x - mu, d1 = x.y - mu, d2 = x.z - mu, d3 = x.w - mu;
    float vs = d0*d0 + d1*d1 + d2*d2 + d3*d3;
    #pragma unroll
    for (int o = 16; o; o >>= 1) vs += __shfl_xor_sync(0xffffffffu, vs, o);
    if ((tid & 31) == 0) red[tid >> 5] = vs;
    __syncthreads();
    if (tid == 0) {
        float tot = 0.f;
        #pragma unroll
        for (int i = 0; i < 8; i++) tot += red[i];
        s_inv = rsqrtf(tot * (1.0f / DM) + EPSF);
    }
    __syncthreads();
    const float inv = s_inv;
    float4 g = *(const float4*)(gamma + tid*4);
    float4 be = *(const float4*)(beta + tid*4);
    float4 y;
    y.x = d0 * inv * g.x + be.x;
    y.y = d1 * inv * g.y + be.y;
    y.z = d2 * inv * g.z + be.z;
    y.w = d3 * inv * g.w + be.w;
    size_t o4 = (size_t)row*DM + tid*4;
    *(float4*)(g_cn + o4) = y;
    __half2* hf = (__half2*)(g_cn_f + o4);
    hf[0] = __floats2half2_rn(y.x, y.y);
    hf[1] = __floats2half2_rn(y.z, y.w);
}

// ================= fp32 -> fp16 (pos_emb) =================
__global__ void __launch_bounds__(256) cvt_half_kernel(const float* __restrict__ src,
                                                       __half* __restrict__ dst, int n4) {
    int i = blockIdx.x * 256 + threadIdx.x;
    if (i >= n4) return;
    float4 x = ((const float4*)src)[i];
    __half2* d = (__half2*)(dst + 4*(size_t)i);
    d[0] = __floats2half2_rn(x.x, x.y);
    d[1] = __floats2half2_rn(x.z, x.w);
}

// ======= weight transpose: z<3 -> fp16 single; z==3 (Wo) -> bf16 hi/lo =======
__global__ void __launch_bounds__(256) wt_split_kernel(const float* __restrict__ Wq,
                                                       const float* __restrict__ Wk,
                                                       const float* __restrict__ Wv,
                                                       const float* __restrict__ Wo) {
    __shared__ float t[32][33];
    const int z = blockIdx.z;
    const float* W = (z == 0) ? Wq : (z == 1) ? Wk : (z == 2) ? Wv : Wo;
    const int n0 = blockIdx.x * 32, k0 = blockIdx.y * 32;
    const int tx = threadIdx.x & 31, ty = threadIdx.x >> 5;
    #pragma unroll
    for (int r = ty; r < 32; r += 8)
        t[r][tx] = W[(size_t)(k0 + r)*DM + n0 + tx];
    __syncthreads();
    if (z < 3) {
        __half* df = g_wt_f + (size_t)z*DM*DM;
        #pragma unroll
        for (int r = ty; r < 32; r += 8)
            df[(size_t)(n0 + r)*DM + k0 + tx] = __float2half_rn(t[tx][r]);
    } else {
        #pragma unroll
        for (int r = ty; r < 32; r += 8) {
            float x = t[tx][r];
            __nv_bfloat16 h = __float2bfloat16(x);
            __nv_bfloat16 l = __float2bfloat16(x - __bfloat162float(h));
            g_wo_h[(size_t)(n0 + r)*DM + k0 + tx] = h;
            g_wo_l[(size_t)(n0 + r)*DM + k0 + tx] = l;
        }
    }
}

// ========= QKV projection: pure fp16 GEMM, k32 chunks, 2-stage 16KB, 2 CTAs/SM =========
#define QTILE  8192
#define QSTG   16384
#define QSMEM  32768
__global__ void __launch_bounds__(256, 2) qkv_f16_kernel(
        __half* __restrict__ qf_, __half* __restrict__ kf_, __half* __restrict__ vf_) {
    const int z = blockIdx.z;
    if (z == 0 && blockIdx.x >= 32) return;

    const __half* B = g_wt_f + (size_t)z*DM*DM;
    __half* dstf;
    int drpb, aoff;
    float scale;
    if (z == 0) { dstf = qf_; drpb = SS; aoff = MEMN; scale = QSCALE; }
    else if (z == 1) { dstf = kf_; drpb = KN; aoff = 0; scale = 1.0f; }
    else { dstf = vf_; drpb = KN; aoff = 0; scale = 1.0f; }

    extern __shared__ __align__(128) char smem[];
    const uint32_t sb = smem_u32(smem);
    const int tid = threadIdx.x, wid = tid >> 5, lane = tid & 31;
    const int wm = wid & 1;
    const int wn = wid >> 1;

    const int m0 = blockIdx.x * 128;
    const int n0 = blockIdx.y * 128;
    const int b  = m0 / drpb;
    const long aRow0 = (long)b * KN + aoff + (m0 % drpb);

    auto issue_chunk = [&](int c, int sidx) {
        uint32_t stg = sb + sidx * QSTG;
        #pragma unroll
        for (int it = 0; it < 4; it++) {
            int g  = it * 256 + tid;
            int tile = g >> 9, u = g & 511;
            int r = u >> 2, cc = u & 3;
            const __half* src;
            long row;
            if (tile == 0) { row = aRow0 + r; src = g_cn_f; }
            else           { row = n0 + r;    src = B; }
            uint32_t dst = stg + tile * QTILE + gsw(r, cc);
            CP_ASYNC16(dst, src + row * DM + c * 32 + cc * 8);
        }
        CP_COMMIT();
    };

    float acc[4][4][4];
    #pragma unroll
    for (int i = 0; i < 4; i++)
        #pragma unroll
        for (int j = 0; j < 4; j++)
            #pragma unroll
            for (int e = 0; e < 4; e++) acc[i][j][e] = 0.f;

    issue_chunk(0, 0);
    for (int c = 0; c < 32; c++) {
        if (c + 1 < 32) issue_chunk(c + 1, (c + 1) & 1);
        else            CP_COMMIT();
        CP_WAIT(1);
        __syncthreads();
        const uint32_t stg = sb + (c & 1) * QSTG;

        #pragma unroll
        for (int ks = 0; ks < 2; ks++) {
            uint32_t af[4][4];
            #pragma unroll
            for (int mt = 0; mt < 4; mt++) {
                int row = wm * 64 + mt * 16 + (lane & 15);
                int s   = ks * 2 + (lane >> 4);
                ldmatrix_x4(af[mt], stg + gsw(row, s));
            }
            uint32_t bq[4][2];
            {
                const int g = lane >> 3;
                #pragma unroll
                for (int np = 0; np < 2; np++) {
                    int brow = wn * 32 + (np * 2 + (g >> 1)) * 8 + (lane & 7);
                    int s    = ks * 2 + (g & 1);
                    uint32_t r[4];
                    ldmatrix_x4(r, stg + QTILE + gsw(brow, s));
                    bq[np*2][0] = r[0]; bq[np*2][1] = r[1];
                    bq[np*2+1][0] = r[2]; bq[np*2+1][1] = r[3];
                }
            }
            #pragma unroll
            for (int nt = 0; nt < 4; nt++)
                #pragma unroll
                for (int mt = 0; mt < 4; mt++)
                    mma_f16(acc[mt][nt], af[mt], bq[nt]);
        }
        __syncthreads();
    }

    #pragma unroll
    for (int mt = 0; mt < 4; mt++) {
        #pragma unroll
        for (int nt = 0; nt < 4; nt++) {
            int row0 = m0 + wm * 64 + mt * 16 + (lane >> 2);
            int n    = n0 + wn * 32 + nt * 8 + (lane & 3) * 2;
            #pragma unroll
            for (int half_ = 0; half_ < 2; half_++) {
                int row = row0 + half_ * 8;
                float v0 = acc[mt][nt][2*half_ + 0] * scale;
                float v1 = acc[mt][nt][2*half_ + 1] * scale;
                int rin = row - b * drpb;
                int hd = n >> 6, d = n & 63;
                size_t off = (((size_t)(b * HN + hd)) * drpb + rin) * DH + d;
                *(__half2*)(dstf + off) = __floats2half2_rn(v0, v1);
            }
        }
    }
}

// ========= Output GEMM + residual: 3-term bf16 split, 2-stage 32KB =========
#define G2TILE  8192
#define G2STG   32768
#define G2SMEM  65536
__global__ void __launch_bounds__(256, 2) out_gemm_kernel(
        float* __restrict__ outf) {
    extern __shared__ __align__(128) char smem[];
    const uint32_t sb = smem_u32(smem);
    const int tid = threadIdx.x, wid = tid >> 5, lane = tid & 31;
    const int wm = wid & 1;
    const int wn = wid >> 1;

    const int m0 = blockIdx.x * 128;
    const int n0 = blockIdx.y * 128;
    const int b  = m0 / SS;
    const long aRow0 = m0;

    auto issue_chunk = [&](int c, int sidx) {
        uint32_t stg = sb + sidx * G2STG;
        #pragma unroll
        for (int it = 0; it < 8; it++) {
            int g  = it * 256 + tid;
            int tile = g >> 9, u = g & 511;
            int r = u >> 2, cc = u & 3;
            const __nv_bfloat16* src;
            long row;
            if (tile == 0)      { row = aRow0 + r; src = g_atth; }
            else if (tile == 1) { row = aRow0 + r; src = g_attl; }
            else if (tile == 2) { row = n0 + r;    src = g_wo_h; }
            else                { row = n0 + r;    src = g_wo_l; }
            uint32_t dst = stg + tile * G2TILE + gsw(r, cc);
            CP_ASYNC16(dst, src + row * DM + c * 32 + cc * 8);
        }
        CP_COMMIT();
    };

    float acc[4][4][4];
    #pragma unroll
    for (int i = 0; i < 4; i++)
        #pragma unroll
        for (int j = 0; j < 4; j++)
            #pragma unroll
            for (int e = 0; e < 4; e++) acc[i][j][e] = 0.f;

    issue_chunk(0, 0);
    for (int c = 0; c < 32; c++) {
        if (c + 1 < 32) issue_chunk(c + 1, (c + 1) & 1);
        else            CP_COMMIT();
        CP_WAIT(1);
        __syncthreads();
        const uint32_t stg = sb + (c & 1) * G2STG;

        #pragma unroll
        for (int ks = 0; ks < 2; ks++) {
            uint32_t ahf[4][4], alf[4][4];
            #pragma unroll
            for (int mt = 0; mt < 4; mt++) {
                int row = wm * 64 + mt * 16 + (lane & 15);
                int s   = ks * 2 + (lane >> 4);
                uint32_t adr = stg + gsw(row, s);
                ldmatrix_x4(ahf[mt], adr);
                ldmatrix_x4(alf[mt], adr + G2TILE);
            }
            #pragma unroll
            for (int nt = 0; nt < 4; nt++) {
                const int g = lane >> 3;
                int brow = wn * 32 + nt * 8 + (lane & 7);
                int s    = ks * 2 + (g & 1);
                uint32_t base = stg + 2 * G2TILE + (uint32_t)(g >> 1) * G2TILE;
                uint32_t r[4];
                ldmatrix_x4(r, base + gsw(brow, s));
                uint32_t bhf[2] = { r[0], r[1] };
                uint32_t blf[2] = { r[2], r[3] };
                #pragma unroll
                for (int mt = 0; mt < 4; mt++) {
                    mma_bf16(acc[mt][nt], alf[mt], bhf);
                    mma_bf16(acc[mt][nt], ahf[mt], blf);
                    mma_bf16(acc[mt][nt], ahf[mt], bhf);
                }
            }
        }
        __syncthreads();
    }

    #pragma unroll
    for (int mt = 0; mt < 4; mt++) {
        #pragma unroll
        for (int nt = 0; nt < 4; nt++) {
            int row0 = m0 + wm * 64 + mt * 16 + (lane >> 2);
            int n    = n0 + wn * 32 + nt * 8 + (lane & 3) * 2;
            #pragma unroll
            for (int half_ = 0; half_ < 2; half_++) {
                int row = row0 + half_ * 8;
                int rin = row - b * SS;
                float* op = outf + (size_t)row * DM + n;
                const float* rp = g_cn + ((size_t)(b * KN + MEMN + rin)) * DM + n;
                op[0] = acc[mt][nt][2*half_ + 0] + rp[0];
                op[1] = acc[mt][nt][2*half_ + 1] + rp[1];
            }
        }
    }
}

// ====== fp16 flash attention: fp16 QP ring, 3 CTAs/SM ======
// smem: [0,16K)   V double buffer (2 x 8K) — buf0 holds Q during prologue
//       [16K,48K) 2 stages x 16K: [K 8K][P 8K]
//       [48K,64K) QP ring 64x128 fp16
#define FSV    0
#define FSSTG  16384
#define FSQP   49152
#define FSMEMH 65536

__device__ __forceinline__ void qp_phase(uint32_t pbase, __half* sQP,
        const uint32_t qf[4][4], int wid, int lane, int hbase) {
    float acc[8][4];
    #pragma unroll
    for (int nt = 0; nt < 8; nt++)
        #pragma unroll
        for (int e = 0; e < 4; e++) acc[nt][e] = 0.f;
    const int g = lane >> 3;
    #pragma unroll
    for (int kt = 0; kt < 4; kt++) {
        uint32_t bh[8][2];
        #pragma unroll
        for (int np = 0; np < 4; np++) {
            int brow = (np * 2 + (g >> 1)) * 8 + (lane & 7);
            uint32_t slot = (uint32_t)((2*kt + (g & 1)) ^ (brow & 7));
            uint32_t r[4];
            ldmatrix_x4(r, pbase + brow*128 + (slot << 4));
            bh[np*2][0] = r[0]; bh[np*2][1] = r[1];
            bh[np*2+1][0] = r[2]; bh[np*2+1][1] = r[3];
        }
        #pragma unroll
        for (int nt = 0; nt < 8; nt++) mma_f16(acc[nt], qf[kt], bh[nt]);
    }
    int r0 = wid*16 + (lane >> 2);
    #pragma unroll
    for (int nt = 0; nt < 8; nt++) {
        int col = hbase + nt*8 + (lane & 3)*2;
        *(__half2*)&sQP[r0*128 + col]       = __floats2half2_rn(acc[nt][0], acc[nt][1]);
        *(__half2*)&sQP[(r0 + 8)*128 + col] = __floats2half2_rn(acc[nt][2], acc[nt][3]);
    }
}

__global__ void __launch_bounds__(128, 3) flash_mma_kernel() {
    extern __shared__ __align__(1024) char sm[];
    const uint32_t sb = smem_u32(sm);
    __half* sQP = (__half*)(sm + FSQP);

    const int b = blockIdx.z, h = blockIdx.y;
    const int qt = 31 - blockIdx.x;
    const int s0 = qt * 64;
    const int tid = threadIdx.x, wid = tid >> 5, lane = tid & 31;
    const int wb0 = 1984 - s0;
    const int ntile = qt + 9;

    const __half* qfb = g_qf + ((size_t)(b*HN + h)*SS + s0)*DH;
    const __half* kfb = g_kf + ((size_t)(b*HN + h)*KN)*DH;
    const __half* vfb = g_vf + ((size_t)(b*HN + h)*KN)*DH;
    const __half* pfb = g_pf + (size_t)b*LPOS*DH;

    auto issue_v = [&](int jtv) {
        if (jtv >= ntile) return;
        int j0v = jtv * 64;
        uint32_t vb = sb + FSV + (uint32_t)(jtv & 1) * 8192;
        #pragma unroll
        for (int l = 0; l < 4; l++) {
            int u = l*128 + tid;
            int rr = (u >> 3) & 63, cc = u & 7;
            uint32_t dst = vb + rr*128 + (((cc ^ (rr & 7))) << 4);
            CP_ASYNC16(dst, vfb + (size_t)(j0v + rr)*DH + cc*8);
        }
    };
    auto issue_kp = [&](int jtn) {
        uint32_t stg = sb + FSSTG + (jtn & 1)*16384;
        int j0n = jtn * 64;
        int pr0 = wb0 + 64*jtn + 64;
        bool kok = (jtn < ntile);
        #pragma unroll
        for (int l = 0; l < 8; l++) {
            int u = l*128 + tid;
            int sel = u >> 9, rr = (u >> 3) & 63, cc = u & 7;
            uint32_t dst = stg + sel*8192 + rr*128 + (((cc ^ (rr & 7))) << 4);
            const __half* src;
            if (sel == 0) {
                if (!kok) continue;
                src = kfb + (size_t)(j0n + rr)*DH + cc*8;
            } else {
                src = pfb + (size_t)(pr0 + rr)*DH + cc*8;
            }
            CP_ASYNC16(dst, src);
        }
    };

    // ---- prologue: Q into V buf0, extract fragments ----
    #pragma unroll
    for (int l = 0; l < 4; l++) {
        int u = l*128 + tid;
        int rr = (u >> 3) & 63, cc = u & 7;
        uint32_t dst = sb + FSV + rr*128 + (((cc ^ (rr & 7))) << 4);
        CP_ASYNC16(dst, qfb + (size_t)rr*DH + cc*8);
    }
    CP_COMMIT();
    CP_WAIT(0);
    __syncthreads();
    uint32_t qf[4][4];
    {
        int arow = wid*16 + (lane & 15);
        #pragma unroll
        for (int kt = 0; kt < 4; kt++) {
            uint32_t slot = (uint32_t)((2*kt + (lane >> 4)) ^ (arow & 7));
            ldmatrix_x4(qf[kt], sb + FSV + arow*128 + (slot << 4));
        }
    }
    __syncthreads();

    // ---- prologue: P_init rows [wb0, wb0+64) into stage1 P slot ----
    #pragma unroll
    for (int l = 0; l < 4; l++) {
        int u = l*128 + tid;
        int rr = (u >> 3) & 63, cc = u & 7;
        uint32_t dst = sb + FSSTG + 16384 + 8192 + rr*128 + (((cc ^ (rr & 7))) << 4);
        CP_ASYNC16(dst, pfb + (size_t)(wb0 + rr)*DH + cc*8);
    }
    CP_COMMIT();
    CP_WAIT(0);
    __syncthreads();
    qp_phase(sb + FSSTG + 16384 + 8192, sQP, qf, wid, lane, 64*((wb0 >> 6) & 1));
    __syncthreads();
    issue_v(0);
    issue_kp(0);
    CP_COMMIT();

    float l0 = 0.f, l1 = 0.f;
    float o[8][4];
    #pragma unroll
    for (int nt = 0; nt < 8; nt++)
        #pragma unroll
        for (int e = 0; e < 4; e++) o[nt][e] = 0.f;

    const int g = lane >> 3;
    for (int jt = 0; jt < ntile; jt++) {
        const int wb = wb0 + 64*jt;
        CP_WAIT(0);
        __syncthreads();    // V(jt), KP(jt) visible; PV(jt-1) complete everywhere
        issue_v(jt + 1);
        issue_kp(jt + 1);
        CP_COMMIT();
        const uint32_t stg = sb + FSSTG + (jt & 1)*16384;
        const uint32_t vbase = sb + FSV + (uint32_t)(jt & 1) * 8192;

        // QP new half
        qp_phase(stg + 8192, sQP, qf, wid, lane, 64*((((wb >> 6) + 1)) & 1));
        __syncwarp();

        // content scores (x4 B loads)
        float sacc[8][4];
        #pragma unroll
        for (int nt = 0; nt < 8; nt++)
            #pragma unroll
            for (int e = 0; e < 4; e++) sacc[nt][e] = 0.f;
        #pragma unroll
        for (int kt = 0; kt < 4; kt++) {
            uint32_t bh[8][2];
            #pragma unroll
            for (int np = 0; np < 4; np++) {
                int brow = (np * 2 + (g >> 1)) * 8 + (lane & 7);
                uint32_t slot = (uint32_t)((2*kt + (g & 1)) ^ (brow & 7));
                uint32_t r[4];
                ldmatrix_x4(r, stg + brow*128 + (slot << 4));
                bh[np*2][0] = r[0]; bh[np*2][1] = r[1];
                bh[np*2+1][0] = r[2]; bh[np*2+1][1] = r[3];
            }
            #pragma unroll
            for (int nt = 0; nt < 8; nt++) mma_f16(sacc[nt], qf[kt], bh[nt]);
        }

        // gather positional diagonals + mask + fixed-shift exp2 softmax
        const int i0 = wid*16 + (lane >> 2);
        const bool lastm = (jt == qt + 8);
        #pragma unroll
        for (int nt = 0; nt < 8; nt++) {
            int jb = nt*8 + (lane & 3)*2;
            int base0 = wb + 63 + jb - i0;
            sacc[nt][0] += __half2float(sQP[i0*128 + (base0 & 127)]);
            sacc[nt][1] += __half2float(sQP[i0*128 + ((base0 + 1) & 127)]);
            sacc[nt][2] += __half2float(sQP[(i0 + 8)*128 + ((base0 - 8) & 127)]);
            sacc[nt][3] += __half2float(sQP[(i0 + 8)*128 + ((base0 - 7) & 127)]);
            if (lastm) {
                if (jb     > i0)     sacc[nt][0] = NEG_BIG;
                if (jb + 1 > i0)     sacc[nt][1] = NEG_BIG;
                if (jb     > i0 + 8) sacc[nt][2] = NEG_BIG;
                if (jb + 1 > i0 + 8) sacc[nt][3] = NEG_BIG;
            }
            sacc[nt][0] = exp2f(sacc[nt][0] - EXP2_SHIFT);
            sacc[nt][1] = exp2f(sacc[nt][1] - EXP2_SHIFT);
            sacc[nt][2] = exp2f(sacc[nt][2] - EXP2_SHIFT);
            sacc[nt][3] = exp2f(sacc[nt][3] - EXP2_SHIFT);
            l0 += sacc[nt][0] + sacc[nt][1];
            l1 += sacc[nt][2] + sacc[nt][3];
        }

        // pack P fp16 fragments from (unnormalized) probs
        uint32_t pf[4][4];
        #pragma unroll
        for (int kt = 0; kt < 4; kt++) {
            #pragma unroll
            for (int e = 0; e < 4; e++) {
                float a0 = sacc[2*kt + (e >> 1)][(e & 1)*2 + 0];
                float a1 = sacc[2*kt + (e >> 1)][(e & 1)*2 + 1];
                __half2 hp = __floats2half2_rn(a0, a1);
                pf[kt][e] = *(uint32_t*)&hp;
            }
        }

        // O += P @ V  (x4 trans B loads)
        #pragma unroll
        for (int kt = 0; kt < 4; kt++) {
            uint32_t bh[8][2];
            #pragma unroll
            for (int np = 0; np < 4; np++) {
                int vrow = kt*16 + (g & 1)*8 + (lane & 7);
                uint32_t slot = (uint32_t)((np*2 + (g >> 1)) ^ (vrow & 7));
                uint32_t r[4];
                ldmatrix_x4_trans(r, vbase + vrow*128 + (slot << 4));
                bh[np*2][0] = r[0]; bh[np*2][1] = r[1];
                bh[np*2+1][0] = r[2]; bh[np*2+1][1] = r[3];
            }
            #pragma unroll
            for (int nt = 0; nt < 8; nt++) mma_f16(o[nt], pf[kt], bh[nt]);
        }
    }

    // epilogue: reduce row sums across quad lanes, normalize, split, write
    l0 += __shfl_xor_sync(0xffffffffu, l0, 1);
    l0 += __shfl_xor_sync(0xffffffffu, l0, 2);
    l1 += __shfl_xor_sync(0xffffffffu, l1, 1);
    l1 += __shfl_xor_sync(0xffffffffu, l1, 2);
    float inv0 = 1.f / l0, inv1 = 1.f / l1;
    const int i0 = wid*16 + (lane >> 2);
    size_t row0 = (size_t)b*SS + s0 + i0;
    #pragma unroll
    for (int nt = 0; nt < 8; nt++) {
        int d = nt*8 + (lane & 3)*2;
        size_t off0 = row0*DM + h*DH + d;
        size_t off1 = (row0 + 8)*DM + h*DH + d;
        store_split2(g_atth, g_attl, off0, o[nt][0]*inv0, o[nt][1]*inv0);
        store_split2(g_atth, g_attl, off1, o[nt][2]*inv1, o[nt][3]*inv1);
    }
}

// =========================== launch ===========================
extern "C" void kernel_launch(void* const* d_in, const int* in_sizes, int n_in,
                              void* d_out, int out_size) {
    const float* hidden = (const float*)d_in[0];
    const float* pos    = (const float*)d_in[1];
    const float* memory = (const float*)d_in[2];
    const float* Wq     = (const float*)d_in[3];
    const float* Wk     = (const float*)d_in[4];
    const float* Wv     = (const float*)d_in[5];
    const float* Wo     = (const float*)d_in[6];
    const float* gamma  = (const float*)d_in[7];
    const float* beta   = (const float*)d_in[8];
    float* out = (float*)d_out;

    static int attr_set = 0;
    if (!attr_set) {
        cudaFuncSetAttribute(qkv_f16_kernel, cudaFuncAttributeMaxDynamicSharedMemorySize, QSMEM);
        cudaFuncSetAttribute(out_gemm_kernel, cudaFuncAttributeMaxDynamicSharedMemorySize, G2SMEM);
        cudaFuncSetAttribute(flash_mma_kernel, cudaFuncAttributeMaxDynamicSharedMemorySize, FSMEMH);
        attr_set = 1;
    }

    __half *qf, *kf, *vf, *pf;
    cudaGetSymbolAddress((void**)&qf, g_qf);
    cudaGetSymbolAddress((void**)&kf, g_kf);
    cudaGetSymbolAddress((void**)&vf, g_vf);
    cudaGetSymbolAddress((void**)&pf, g_pf);

    ln_kernel<<<BB*KN, 256>>>(hidden, memory, gamma, beta);
    wt_split_kernel<<<dim3(DM/32, DM/32, 4), 256>>>(Wq, Wk, Wv, Wo);
    cvt_half_kernel<<<(BB*LPOS*DH/4 + 255)/256, 256>>>(pos, pf, BB*LPOS*DH/4);

    // merged Q/K/V projections, pure fp16; Q scaled by 2^-5 * log2e in epilogue
    qkv_f16_kernel<<<dim3((BB*KN)/128, DM/128, 3), 256, QSMEM>>>(qf, kf, vf);

    flash_mma_kernel<<<dim3(SS/64, HN, BB), 128, FSMEMH>>>();

    // Output GEMM + residual (3-term bf16)
    out_gemm_kernel<<<dim3((BB*SS)/128, DM/128, 1), 256, G2SMEM>>>(out);
}

// round 17
// speedup vs baseline: 1.2818x; 1.2818x over previous
#include <cuda_runtime.h>
#include <cuda_bf16.h>
#include <cuda_fp16.h>
#include <math.h>
#include <stdint.h>

#define BB    2
#define SS    2048
#define MEMN  512
#define KN    2560
#define HN    16
#define DH    64
#define DM    1024
#define LPOS  (2*KN-1)        /* 5119 */
#define SCALE_F 0.03125f      /* 1/sqrt(1024) = 2^-5 */
#define QSCALE  (0.03125f * 1.44269504f)   /* fold log2e into Q */
#define EXP2_SHIFT 5.77078016f             /* 4 * log2e */
#define EPSF  1e-5f
#define NEG_BIG (-1e30f)

// ------------------- device scratch (no allocation allowed) -------------------
__device__ float g_cn [BB*KN*DM];        // LN([memory; hidden]) fp32 (residual)
__device__ __align__(16) __half g_cn_f [BB*KN*DM];
__device__ __align__(16) __half g_qf[BB*HN*SS*DH];
__device__ __align__(16) __half g_kf[BB*HN*KN*DH];
__device__ __align__(16) __half g_vf[BB*HN*KN*DH];
__device__ __align__(16) __half g_pf[BB*LPOS*DH];
__device__ __align__(16) __half g_wt_f [4*DM*DM];      // Wq/Wk/Wv/Wo transposed fp16
__device__ __align__(16) __half g_att_f[BB*SS*DM];     // attention output fp16

// ========================= helpers =========================
__device__ __forceinline__ uint32_t smem_u32(const void* p) {
    uint32_t a;
    asm("{ .reg .u64 t; cvta.to.shared.u64 t, %1; cvt.u32.u64 %0, t; }" : "=r"(a) : "l"(p));
    return a;
}
__device__ __forceinline__ void ldmatrix_x4(uint32_t* r, uint32_t addr) {
    asm volatile("ldmatrix.sync.aligned.m8n8.x4.shared.b16 {%0,%1,%2,%3}, [%4];"
        : "=r"(r[0]), "=r"(r[1]), "=r"(r[2]), "=r"(r[3]) : "r"(addr));
}
__device__ __forceinline__ void ldmatrix_x4_trans(uint32_t* r, uint32_t addr) {
    asm volatile("ldmatrix.sync.aligned.m8n8.x4.trans.shared.b16 {%0,%1,%2,%3}, [%4];"
        : "=r"(r[0]), "=r"(r[1]), "=r"(r[2]), "=r"(r[3]) : "r"(addr));
}
__device__ __forceinline__ void mma_f16(float* d, const uint32_t* a, const uint32_t* b) {
    asm volatile(
        "mma.sync.aligned.m16n8k16.row.col.f32.f16.f16.f32 "
        "{%0,%1,%2,%3}, {%4,%5,%6,%7}, {%8,%9}, {%0,%1,%2,%3};"
        : "+f"(d[0]), "+f"(d[1]), "+f"(d[2]), "+f"(d[3])
        : "r"(a[0]), "r"(a[1]), "r"(a[2]), "r"(a[3]), "r"(b[0]), "r"(b[1]));
}
#define CP_ASYNC16(dst, src) \
    asm volatile("cp.async.cg.shared.global [%0], [%1], 16;" :: "r"(dst), "l"(src))
#define CP_COMMIT() asm volatile("cp.async.commit_group;" ::: "memory")
#define CP_WAIT(N)  asm volatile("cp.async.wait_group %0;" :: "n"(N) : "memory")

// 128B-row tile swizzle: r in [0,128), cc slot in [0,8) (16B units). Tile = 16KB.
__device__ __forceinline__ uint32_t fsw(int r, int cc) {
    return (uint32_t)(r * 128 + ((cc ^ (r & 7)) << 4));
}

// =========================== LayerNorm (+ fp16 store) ===========================
__global__ void __launch_bounds__(256) ln_kernel(const float* __restrict__ hidden,
                                                 const float* __restrict__ memory,
                                                 const float* __restrict__ gamma,
                                                 const float* __restrict__ beta) {
    __shared__ float red[8];
    __shared__ float s_mu, s_inv;
    const int row = blockIdx.x;
    const int b = row / KN, t = row % KN;
    const float* src = (t < MEMN) ? (memory + ((size_t)b*MEMN + t)*DM)
                                  : (hidden + ((size_t)b*SS + (t - MEMN))*DM);
    const int tid = threadIdx.x;
    float4 x = *(const float4*)(src + tid*4);

    float s = x.x + x.y + x.z + x.w;
    #pragma unroll
    for (int o = 16; o; o >>= 1) s += __shfl_xor_sync(0xffffffffu, s, o);
    if ((tid & 31) == 0) red[tid >> 5] = s;
    __syncthreads();
    if (tid == 0) {
        float tot = 0.f;
        #pragma unroll
        for (int i = 0; i < 8; i++) tot += red[i];
        s_mu = tot * (1.0f / DM);
    }
    __syncthreads();
    const float mu = s_mu;
    float d0 = x.x - mu, d1 = x.y - mu, d2 = x.z - mu, d3 = x.w - mu;
    float vs = d0*d0 + d1*d1 + d2*d2 + d3*d3;
    #pragma unroll
    for (int o = 16; o; o >>= 1) vs += __shfl_xor_sync(0xffffffffu, vs, o);
    if ((tid & 31) == 0) red[tid >> 5] = vs;
    __syncthreads();
    if (tid == 0) {
        float tot = 0.f;
        #pragma unroll
        for (int i = 0; i < 8; i++) tot += red[i];
        s_inv = rsqrtf(tot * (1.0f / DM) + EPSF);
    }
    __syncthreads();
    const float inv = s_inv;
    float4 g = *(const float4*)(gamma + tid*4);
    float4 be = *(const float4*)(beta + tid*4);
    float4 y;
    y.x = d0 * inv * g.x + be.x;
    y.y = d1 * inv * g.y + be.y;
    y.z = d2 * inv * g.z + be.z;
    y.w = d3 * inv * g.w + be.w;
    size_t o4 = (size_t)row*DM + tid*4;
    *(float4*)(g_cn + o4) = y;
    __half2* hf = (__half2*)(g_cn_f + o4);
    hf[0] = __floats2half2_rn(y.x, y.y);
    hf[1] = __floats2half2_rn(y.z, y.w);
}

// ================= fp32 -> fp16 (pos_emb) =================
__global__ void __launch_bounds__(256) cvt_half_kernel(const float* __restrict__ src,
                                                       __half* __restrict__ dst, int n4) {
    int i = blockIdx.x * 256 + threadIdx.x;
    if (i >= n4) return;
    float4 x = ((const float4*)src)[i];
    __half2* d = (__half2*)(dst + 4*(size_t)i);
    d[0] = __floats2half2_rn(x.x, x.y);
    d[1] = __floats2half2_rn(x.z, x.w);
}

// ======= weight transpose -> fp16: Wt[n][k] = fp16(W[k][n]) =======
__global__ void __launch_bounds__(256) wt_split_kernel(const float* __restrict__ Wq,
                                                       const float* __restrict__ Wk,
                                                       const float* __restrict__ Wv,
                                                       const float* __restrict__ Wo) {
    __shared__ float t[32][33];
    const int z = blockIdx.z;
    const float* W = (z == 0) ? Wq : (z == 1) ? Wk : (z == 2) ? Wv : Wo;
    const int n0 = blockIdx.x * 32, k0 = blockIdx.y * 32;
    const int tx = threadIdx.x & 31, ty = threadIdx.x >> 5;
    #pragma unroll
    for (int r = ty; r < 32; r += 8)
        t[r][tx] = W[(size_t)(k0 + r)*DM + n0 + tx];
    __syncthreads();
    __half* df = g_wt_f + (size_t)z*DM*DM;
    #pragma unroll
    for (int r = ty; r < 32; r += 8)
        df[(size_t)(n0 + r)*DM + k0 + tx] = __float2half_rn(t[tx][r]);
}

// ========= fp16 GEMM: k64 chunks, 2-stage 32KB, 2 CTAs/SM =========
// mode 0 (grid 40,8,3): QKV. z==0 Q (scaled, 32 x-tiles), z==1 K, z==2 V.
// mode 1 (grid 32,8,1): out = att @ Wo^T + residual, fp32 out.
#define GTILE  16384
#define GSTG   32768
#define GSMEM  65536
__global__ void __launch_bounds__(256, 2) gemm_f16_kernel(
        __half* __restrict__ qf_, __half* __restrict__ kf_, __half* __restrict__ vf_,
        float* __restrict__ outf, int mode) {
    const int z = blockIdx.z;
    if (mode == 0 && z == 0 && blockIdx.x >= 32) return;

    const __half *A, *B;
    __half* dstf = nullptr;
    int drpb, aoff;
    float scale = 1.0f;
    if (mode == 0) {
        A = g_cn_f;
        B = g_wt_f + (size_t)z*DM*DM;
        if (z == 0) { dstf = qf_; drpb = SS; aoff = MEMN; scale = QSCALE; }
        else if (z == 1) { dstf = kf_; drpb = KN; aoff = 0; }
        else { dstf = vf_; drpb = KN; aoff = 0; }
    } else {
        A = g_att_f;
        B = g_wt_f + 3*(size_t)DM*DM;
        drpb = SS; aoff = 0;
    }

    extern __shared__ __align__(128) char smem[];
    const uint32_t sb = smem_u32(smem);
    const int tid = threadIdx.x, wid = tid >> 5, lane = tid & 31;
    const int wm = wid & 1;
    const int wn = wid >> 1;

    const int m0 = blockIdx.x * 128;
    const int n0 = blockIdx.y * 128;
    const int b  = m0 / drpb;
    const long aRow0 = (mode == 0) ? ((long)b * KN + aoff + (m0 % drpb)) : (long)m0;

    auto issue_chunk = [&](int c, int sidx) {
        uint32_t stg = sb + sidx * GSTG;
        #pragma unroll
        for (int it = 0; it < 8; it++) {
            int gg = it * 256 + tid;
            int tile = gg >> 10, u = gg & 1023;
            int r = u >> 3, cc = u & 7;
            const __half* src;
            long row;
            if (tile == 0) { row = aRow0 + r; src = A; }
            else           { row = n0 + r;    src = B; }
            uint32_t dst = stg + tile * GTILE + fsw(r, cc);
            CP_ASYNC16(dst, src + row * DM + c * 64 + cc * 8);
        }
        CP_COMMIT();
    };

    float acc[4][4][4];
    #pragma unroll
    for (int i = 0; i < 4; i++)
        #pragma unroll
        for (int j = 0; j < 4; j++)
            #pragma unroll
            for (int e = 0; e < 4; e++) acc[i][j][e] = 0.f;

    issue_chunk(0, 0);
    for (int c = 0; c < 16; c++) {
        if (c + 1 < 16) issue_chunk(c + 1, (c + 1) & 1);
        else            CP_COMMIT();
        CP_WAIT(1);
        __syncthreads();
        const uint32_t stg = sb + (c & 1) * GSTG;

        #pragma unroll
        for (int ks = 0; ks < 4; ks++) {
            uint32_t af[4][4];
            #pragma unroll
            for (int mt = 0; mt < 4; mt++) {
                int row = wm * 64 + mt * 16 + (lane & 15);
                int slot = (2*ks + (lane >> 4)) ^ (row & 7);
                ldmatrix_x4(af[mt], stg + (uint32_t)(row*128 + slot*16));
            }
            uint32_t bq[4][2];
            {
                const int g = lane >> 3;
                #pragma unroll
                for (int np = 0; np < 2; np++) {
                    int brow = wn * 32 + (np * 2 + (g >> 1)) * 8 + (lane & 7);
                    int slot = (2*ks + (g & 1)) ^ (brow & 7);
                    uint32_t r[4];
                    ldmatrix_x4(r, stg + GTILE + (uint32_t)(brow*128 + slot*16));
                    bq[np*2][0] = r[0]; bq[np*2][1] = r[1];
                    bq[np*2+1][0] = r[2]; bq[np*2+1][1] = r[3];
                }
            }
            #pragma unroll
            for (int nt = 0; nt < 4; nt++)
                #pragma unroll
                for (int mt = 0; mt < 4; mt++)
                    mma_f16(acc[mt][nt], af[mt], bq[nt]);
        }
        __syncthreads();
    }

    #pragma unroll
    for (int mt = 0; mt < 4; mt++) {
        #pragma unroll
        for (int nt = 0; nt < 4; nt++) {
            int row0 = m0 + wm * 64 + mt * 16 + (lane >> 2);
            int n    = n0 + wn * 32 + nt * 8 + (lane & 3) * 2;
            #pragma unroll
            for (int half_ = 0; half_ < 2; half_++) {
                int row = row0 + half_ * 8;
                float v0 = acc[mt][nt][2*half_ + 0] * scale;
                float v1 = acc[mt][nt][2*half_ + 1] * scale;
                int rin = row - b * drpb;
                if (mode == 0) {
                    int hd = n >> 6, d = n & 63;
                    size_t off = (((size_t)(b * HN + hd)) * drpb + rin) * DH + d;
                    *(__half2*)(dstf + off) = __floats2half2_rn(v0, v1);
                } else {
                    float* op = outf + (size_t)row * DM + n;
                    const float* rp = g_cn + ((size_t)(b * KN + MEMN + rin)) * DM + n;
                    op[0] = v0 + rp[0];
                    op[1] = v1 + rp[1];
                }
            }
        }
    }
}

// ============== fp16 flash attention (R15 config): x4 LDSM, single-sync, fp32 QP ring ==============
// smem: [0,16K)   V double buffer (2 x 8K) — buf0 holds Q during prologue
//       [16K,48K) 2 stages x 16K: [K 8K][P 8K]
//       [48K,80K) QP ring 64x128 fp32
#define FSV    0
#define FSSTG  16384
#define FSQP   49152
#define FSMEMH 81920

__device__ __forceinline__ void qp_phase(uint32_t pbase, float* sQP,
        const uint32_t qf[4][4], int wid, int lane, int hbase) {
    float acc[8][4];
    #pragma unroll
    for (int nt = 0; nt < 8; nt++)
        #pragma unroll
        for (int e = 0; e < 4; e++) acc[nt][e] = 0.f;
    const int g = lane >> 3;
    #pragma unroll
    for (int kt = 0; kt < 4; kt++) {
        uint32_t bh[8][2];
        #pragma unroll
        for (int np = 0; np < 4; np++) {
            int brow = (np * 2 + (g >> 1)) * 8 + (lane & 7);
            uint32_t slot = (uint32_t)((2*kt + (g & 1)) ^ (brow & 7));
            uint32_t r[4];
            ldmatrix_x4(r, pbase + brow*128 + (slot << 4));
            bh[np*2][0] = r[0]; bh[np*2][1] = r[1];
            bh[np*2+1][0] = r[2]; bh[np*2+1][1] = r[3];
        }
        #pragma unroll
        for (int nt = 0; nt < 8; nt++) mma_f16(acc[nt], qf[kt], bh[nt]);
    }
    int r0 = wid*16 + (lane >> 2);
    #pragma unroll
    for (int nt = 0; nt < 8; nt++) {
        int col = hbase + nt*8 + (lane & 3)*2;
        *(float2*)&sQP[r0*128 + col]       = make_float2(acc[nt][0], acc[nt][1]);
        *(float2*)&sQP[(r0 + 8)*128 + col] = make_float2(acc[nt][2], acc[nt][3]);
    }
}

__global__ void __launch_bounds__(128, 2) flash_mma_kernel() {
    extern __shared__ __align__(1024) char sm[];
    const uint32_t sb = smem_u32(sm);
    float* sQP = (float*)(sm + FSQP);

    const int b = blockIdx.z, h = blockIdx.y;
    const int qt = 31 - blockIdx.x;
    const int s0 = qt * 64;
    const int tid = threadIdx.x, wid = tid >> 5, lane = tid & 31;
    const int wb0 = 1984 - s0;
    const int ntile = qt + 9;

    const __half* qfb = g_qf + ((size_t)(b*HN + h)*SS + s0)*DH;
    const __half* kfb = g_kf + ((size_t)(b*HN + h)*KN)*DH;
    const __half* vfb = g_vf + ((size_t)(b*HN + h)*KN)*DH;
    const __half* pfb = g_pf + (size_t)b*LPOS*DH;

    auto issue_v = [&](int jtv) {
        if (jtv >= ntile) return;
        int j0v = jtv * 64;
        uint32_t vb = sb + FSV + (uint32_t)(jtv & 1) * 8192;
        #pragma unroll
        for (int l = 0; l < 4; l++) {
            int u = l*128 + tid;
            int rr = (u >> 3) & 63, cc = u & 7;
            uint32_t dst = vb + rr*128 + (((cc ^ (rr & 7))) << 4);
            CP_ASYNC16(dst, vfb + (size_t)(j0v + rr)*DH + cc*8);
        }
    };
    auto issue_kp = [&](int jtn) {
        uint32_t stg = sb + FSSTG + (jtn & 1)*16384;
        int j0n = jtn * 64;
        int pr0 = wb0 + 64*jtn + 64;
        bool kok = (jtn < ntile);
        #pragma unroll
        for (int l = 0; l < 8; l++) {
            int u = l*128 + tid;
            int sel = u >> 9, rr = (u >> 3) & 63, cc = u & 7;
            uint32_t dst = stg + sel*8192 + rr*128 + (((cc ^ (rr & 7))) << 4);
            const __half* src;
            if (sel == 0) {
                if (!kok) continue;
                src = kfb + (size_t)(j0n + rr)*DH + cc*8;
            } else {
                src = pfb + (size_t)(pr0 + rr)*DH + cc*8;
            }
            CP_ASYNC16(dst, src);
        }
    };

    // ---- prologue: Q into V buf0, extract fragments ----
    #pragma unroll
    for (int l = 0; l < 4; l++) {
        int u = l*128 + tid;
        int rr = (u >> 3) & 63, cc = u & 7;
        uint32_t dst = sb + FSV + rr*128 + (((cc ^ (rr & 7))) << 4);
        CP_ASYNC16(dst, qfb + (size_t)rr*DH + cc*8);
    }
    CP_COMMIT();
    CP_WAIT(0);
    __syncthreads();
    uint32_t qf[4][4];
    {
        int arow = wid*16 + (lane & 15);
        #pragma unroll
        for (int kt = 0; kt < 4; kt++) {
            uint32_t slot = (uint32_t)((2*kt + (lane >> 4)) ^ (arow & 7));
            ldmatrix_x4(qf[kt], sb + FSV + arow*128 + (slot << 4));
        }
    }
    __syncthreads();

    // ---- prologue: P_init rows [wb0, wb0+64) into stage1 P slot ----
    #pragma unroll
    for (int l = 0; l < 4; l++) {
        int u = l*128 + tid;
        int rr = (u >> 3) & 63, cc = u & 7;
        uint32_t dst = sb + FSSTG + 16384 + 8192 + rr*128 + (((cc ^ (rr & 7))) << 4);
        CP_ASYNC16(dst, pfb + (size_t)(wb0 + rr)*DH + cc*8);
    }
    CP_COMMIT();
    CP_WAIT(0);
    __syncthreads();
    qp_phase(sb + FSSTG + 16384 + 8192, sQP, qf, wid, lane, 64*((wb0 >> 6) & 1));
    __syncthreads();
    issue_v(0);
    issue_kp(0);
    CP_COMMIT();

    float l0 = 0.f, l1 = 0.f;
    float o[8][4];
    #pragma unroll
    for (int nt = 0; nt < 8; nt++)
        #pragma unroll
        for (int e = 0; e < 4; e++) o[nt][e] = 0.f;

    const int g = lane >> 3;
    for (int jt = 0; jt < ntile; jt++) {
        const int wb = wb0 + 64*jt;
        CP_WAIT(0);
        __syncthreads();    // V(jt), KP(jt) visible; PV(jt-1) complete everywhere
        issue_v(jt + 1);
        issue_kp(jt + 1);
        CP_COMMIT();
        const uint32_t stg = sb + FSSTG + (jt & 1)*16384;
        const uint32_t vbase = sb + FSV + (uint32_t)(jt & 1) * 8192;

        // QP new half
        qp_phase(stg + 8192, sQP, qf, wid, lane, 64*((((wb >> 6) + 1)) & 1));
        __syncwarp();

        // content scores (x4 B loads)
        float sacc[8][4];
        #pragma unroll
        for (int nt = 0; nt < 8; nt++)
            #pragma unroll
            for (int e = 0; e < 4; e++) sacc[nt][e] = 0.f;
        #pragma unroll
        for (int kt = 0; kt < 4; kt++) {
            uint32_t bh[8][2];
            #pragma unroll
            for (int np = 0; np < 4; np++) {
                int brow = (np * 2 + (g >> 1)) * 8 + (lane & 7);
                uint32_t slot = (uint32_t)((2*kt + (g & 1)) ^ (brow & 7));
                uint32_t r[4];
                ldmatrix_x4(r, stg + brow*128 + (slot << 4));
                bh[np*2][0] = r[0]; bh[np*2][1] = r[1];
                bh[np*2+1][0] = r[2]; bh[np*2+1][1] = r[3];
            }
            #pragma unroll
            for (int nt = 0; nt < 8; nt++) mma_f16(sacc[nt], qf[kt], bh[nt]);
        }

        // gather positional diagonals + mask + fixed-shift exp2 softmax
        const int i0 = wid*16 + (lane >> 2);
        const bool lastm = (jt == qt + 8);
        #pragma unroll
        for (int nt = 0; nt < 8; nt++) {
            int jb = nt*8 + (lane & 3)*2;
            int base0 = wb + 63 + jb - i0;
            sacc[nt][0] += sQP[i0*128 + (base0 & 127)];
            sacc[nt][1] += sQP[i0*128 + ((base0 + 1) & 127)];
            sacc[nt][2] += sQP[(i0 + 8)*128 + ((base0 - 8) & 127)];
            sacc[nt][3] += sQP[(i0 + 8)*128 + ((base0 - 7) & 127)];
            if (lastm) {
                if (jb     > i0)     sacc[nt][0] = NEG_BIG;
                if (jb + 1 > i0)     sacc[nt][1] = NEG_BIG;
                if (jb     > i0 + 8) sacc[nt][2] = NEG_BIG;
                if (jb + 1 > i0 + 8) sacc[nt][3] = NEG_BIG;
            }
            sacc[nt][0] = exp2f(sacc[nt][0] - EXP2_SHIFT);
            sacc[nt][1] = exp2f(sacc[nt][1] - EXP2_SHIFT);
            sacc[nt][2] = exp2f(sacc[nt][2] - EXP2_SHIFT);
            sacc[nt][3] = exp2f(sacc[nt][3] - EXP2_SHIFT);
            l0 += sacc[nt][0] + sacc[nt][1];
            l1 += sacc[nt][2] + sacc[nt][3];
        }

        // pack P fp16 fragments from (unnormalized) probs
        uint32_t pf[4][4];
        #pragma unroll
        for (int kt = 0; kt < 4; kt++) {
            #pragma unroll
            for (int e = 0; e < 4; e++) {
                float a0 = sacc[2*kt + (e >> 1)][(e & 1)*2 + 0];
                float a1 = sacc[2*kt + (e >> 1)][(e & 1)*2 + 1];
                __half2 hp = __floats2half2_rn(a0, a1);
                pf[kt][e] = *(uint32_t*)&hp;
            }
        }

        // O += P @ V  (x4 trans B loads)
        #pragma unroll
        for (int kt = 0; kt < 4; kt++) {
            uint32_t bh[8][2];
            #pragma unroll
            for (int np = 0; np < 4; np++) {
                int vrow = kt*16 + (g & 1)*8 + (lane & 7);
                uint32_t slot = (uint32_t)((np*2 + (g >> 1)) ^ (vrow & 7));
                uint32_t r[4];
                ldmatrix_x4_trans(r, vbase + vrow*128 + (slot << 4));
                bh[np*2][0] = r[0]; bh[np*2][1] = r[1];
                bh[np*2+1][0] = r[2]; bh[np*2+1][1] = r[3];
            }
            #pragma unroll
            for (int nt = 0; nt < 8; nt++) mma_f16(o[nt], pf[kt], bh[nt]);
        }
    }

    // epilogue: reduce row sums across quad lanes, normalize, write fp16 att
    l0 += __shfl_xor_sync(0xffffffffu, l0, 1);
    l0 += __shfl_xor_sync(0xffffffffu, l0, 2);
    l1 += __shfl_xor_sync(0xffffffffu, l1, 1);
    l1 += __shfl_xor_sync(0xffffffffu, l1, 2);
    float inv0 = 1.f / l0, inv1 = 1.f / l1;
    const int i0 = wid*16 + (lane >> 2);
    size_t row0 = (size_t)b*SS + s0 + i0;
    #pragma unroll
    for (int nt = 0; nt < 8; nt++) {
        int d = nt*8 + (lane & 3)*2;
        *(__half2*)(g_att_f + row0*DM + h*DH + d) =
            __floats2half2_rn(o[nt][0]*inv0, o[nt][1]*inv0);
        *(__half2*)(g_att_f + (row0 + 8)*DM + h*DH + d) =
            __floats2half2_rn(o[nt][2]*inv1, o[nt][3]*inv1);
    }
}

// =========================== launch ===========================
extern "C" void kernel_launch(void* const* d_in, const int* in_sizes, int n_in,
                              void* d_out, int out_size) {
    const float* hidden = (const float*)d_in[0];
    const float* pos    = (const float*)d_in[1];
    const float* memory = (const float*)d_in[2];
    const float* Wq     = (const float*)d_in[3];
    const float* Wk     = (const float*)d_in[4];
    const float* Wv     = (const float*)d_in[5];
    const float* Wo     = (const float*)d_in[6];
    const float* gamma  = (const float*)d_in[7];
    const float* beta   = (const float*)d_in[8];
    float* out = (float*)d_out;

    static int attr_set = 0;
    if (!attr_set) {
        cudaFuncSetAttribute(gemm_f16_kernel, cudaFuncAttributeMaxDynamicSharedMemorySize, GSMEM);
        cudaFuncSetAttribute(flash_mma_kernel, cudaFuncAttributeMaxDynamicSharedMemorySize, FSMEMH);
        attr_set = 1;
    }

    __half *qf, *kf, *vf, *pf;
    cudaGetSymbolAddress((void**)&qf, g_qf);
    cudaGetSymbolAddress((void**)&kf, g_kf);
    cudaGetSymbolAddress((void**)&vf, g_vf);
    cudaGetSymbolAddress((void**)&pf, g_pf);

    ln_kernel<<<BB*KN, 256>>>(hidden, memory, gamma, beta);
    wt_split_kernel<<<dim3(DM/32, DM/32, 4), 256>>>(Wq, Wk, Wv, Wo);
    cvt_half_kernel<<<(BB*LPOS*DH/4 + 255)/256, 256>>>(pos, pf, BB*LPOS*DH/4);

    // merged Q/K/V projections, pure fp16, k64 chunks
    gemm_f16_kernel<<<dim3((BB*KN)/128, DM/128, 3), 256, GSMEM>>>(qf, kf, vf, nullptr, 0);

    flash_mma_kernel<<<dim3(SS/64, HN, BB), 128, FSMEMH>>>();

    // Output GEMM + residual, pure fp16
    gemm_f16_kernel<<<dim3((BB*SS)/128, DM/128, 1), 256, GSMEM>>>(nullptr, nullptr, nullptr, out, 1);
}